// round 6
// baseline (speedup 1.0000x reference)
#include <cuda_runtime.h>
#include <cuda_bf16.h>
#include <cstdint>

// out[i,j] = 2*x[i,j] + 5 - (i+j), x: [8192, 8192] fp32
// HBM-streaming kernel: 4 float4 per thread (MLP=4, front-batched loads),
// streaming cache hints (read-once / write-once data).

static constexpr int N_COLS = 8192;
static constexpr int COLS4  = N_COLS / 4;                       // 2048 float4/row
static constexpr unsigned int TOTAL4 = 8192u * COLS4;           // 16,777,216
static constexpr unsigned int QUART4 = TOTAL4 / 4;              // 4,194,304

__device__ __forceinline__ float4 compute(unsigned int idx, float4 v)
{
    unsigned int row  = idx >> 11;          // idx / 2048
    unsigned int col  = (idx & 2047u) << 2; // first scalar column of this float4
    float base = 5.0f - (float)(row + col);
    float4 o;
    o.x = fmaf(2.0f, v.x, base);
    o.y = fmaf(2.0f, v.y, base - 1.0f);
    o.z = fmaf(2.0f, v.z, base - 2.0f);
    o.w = fmaf(2.0f, v.w, base - 3.0f);
    return o;
}

__global__ __launch_bounds__(256) void fused_map_kernel(
    const float4* __restrict__ in, float4* __restrict__ out)
{
    unsigned int t = blockIdx.x * 256u + threadIdx.x;   // 0 .. QUART4-1
    unsigned int i0 = t;
    unsigned int i1 = t + QUART4;
    unsigned int i2 = t + 2u * QUART4;
    unsigned int i3 = t + 3u * QUART4;

    // Front-batched independent loads (MLP=4), streaming (evict-first) policy.
    float4 v0 = __ldcs(in + i0);
    float4 v1 = __ldcs(in + i1);
    float4 v2 = __ldcs(in + i2);
    float4 v3 = __ldcs(in + i3);

    float4 o0 = compute(i0, v0);
    float4 o1 = compute(i1, v1);
    float4 o2 = compute(i2, v2);
    float4 o3 = compute(i3, v3);

    __stcs(out + i0, o0);
    __stcs(out + i1, o1);
    __stcs(out + i2, o2);
    __stcs(out + i3, o3);
}

extern "C" void kernel_launch(void* const* d_in, const int* in_sizes, int n_in,
                              void* d_out, int out_size)
{
    const float4* in  = (const float4*)d_in[0];
    float4*       out = (float4*)d_out;
    unsigned int blocks = QUART4 / 256;   // 16384 blocks
    fused_map_kernel<<<blocks, 256>>>(in, out);
}

// round 7
// speedup vs baseline: 1.0167x; 1.0167x over previous
#include <cuda_runtime.h>
#include <cuda_bf16.h>
#include <cstdint>

// out[i,j] = 2*x[i,j] + 5 - (i+j), x: [8192, 8192] fp32
// HBM-streaming kernel at ~90% of spec BW. MLP=2 front-batched loads with
// "last-use" L2 hint (line freed after single read), evict-first stores.

static constexpr int N_COLS = 8192;
static constexpr int COLS4  = N_COLS / 4;                       // 2048 float4/row
static constexpr unsigned int TOTAL4 = 8192u * COLS4;           // 16,777,216
static constexpr unsigned int HALF4  = TOTAL4 / 2;              // 8,388,608

__device__ __forceinline__ float4 ld_lu(const float4* p)
{
    float4 v;
    asm volatile("ld.global.lu.v4.f32 {%0,%1,%2,%3}, [%4];"
                 : "=f"(v.x), "=f"(v.y), "=f"(v.z), "=f"(v.w)
                 : "l"(p));
    return v;
}

__device__ __forceinline__ float4 compute(unsigned int idx, float4 v)
{
    unsigned int row  = idx >> 11;          // idx / 2048
    unsigned int col  = (idx & 2047u) << 2; // first scalar column of this float4
    float base = 5.0f - (float)(row + col);
    float4 o;
    o.x = fmaf(2.0f, v.x, base);
    o.y = fmaf(2.0f, v.y, base - 1.0f);
    o.z = fmaf(2.0f, v.z, base - 2.0f);
    o.w = fmaf(2.0f, v.w, base - 3.0f);
    return o;
}

__global__ __launch_bounds__(512) void fused_map_kernel(
    const float4* __restrict__ in, float4* __restrict__ out)
{
    unsigned int t = blockIdx.x * 512u + threadIdx.x;   // 0 .. HALF4-1
    unsigned int i0 = t;
    unsigned int i1 = t + HALF4;

    // Front-batched independent loads (MLP=2), last-use policy: L2 line is
    // dropped after the single read instead of lingering.
    float4 v0 = ld_lu(in + i0);
    float4 v1 = ld_lu(in + i1);

    float4 o0 = compute(i0, v0);
    float4 o1 = compute(i1, v1);

    // Evict-first stores: write-once data should not displace anything.
    __stcs(out + i0, o0);
    __stcs(out + i1, o1);
}

extern "C" void kernel_launch(void* const* d_in, const int* in_sizes, int n_in,
                              void* d_out, int out_size)
{
    const float4* in  = (const float4*)d_in[0];
    float4*       out = (float4*)d_out;
    unsigned int blocks = HALF4 / 512;   // 16384 blocks
    fused_map_kernel<<<blocks, 512>>>(in, out);
}